// round 3
// baseline (speedup 1.0000x reference)
#include <cuda_runtime.h>

#define NEG_SLOPE 0.2f

// x: [B=8, C=256, H=128, W=128] f32
static constexpr int NROWS = 2048;      // B*C
static constexpr int ROW_ELEMS = 16384; // H*W
static constexpr int ROW_VEC4 = ROW_ELEMS / 4; // 4096
static constexpr int B = 8;
static constexpr int C = 256;
static constexpr int CS = 16;

static constexpr int GRID = 512;            // single wave: <=8 CTAs/SM needed, we use ~3.5
static constexpr int ROWS_PER_CTA = NROWS / GRID; // 4

__device__ float g_y[NROWS];            // pooled means
__device__ float g_gate[NROWS];         // sigmoid gates
__device__ unsigned int g_cnt1;         // pooling-done counter (self-reset)
__device__ unsigned int g_cnt2;         // scale-done counter  (self-reset)
__device__ unsigned int g_flag;         // gates-ready flag    (self-reset)

__global__ __launch_bounds__(256) void se_fused_kernel(const float* __restrict__ x,
                                                       const float* __restrict__ w1,
                                                       const float* __restrict__ b1,
                                                       const float* __restrict__ w2,
                                                       const float* __restrict__ b2,
                                                       float* __restrict__ out) {
    const int tid = threadIdx.x;
    const int cta = blockIdx.x;
    const int row0 = cta * ROWS_PER_CTA;

    __shared__ float warp_sums[8];
    __shared__ bool is_last;
    __shared__ float sh_y[NROWS];   // 8 KB (FC tail only)
    __shared__ float sh_y1[B * CS];

    // ---------------- Phase 1: pool ROWS_PER_CTA rows ----------------
#pragma unroll
    for (int r = 0; r < ROWS_PER_CTA; r++) {
        const int row = row0 + r;
        const float4* __restrict__ xr =
            reinterpret_cast<const float4*>(x) + (size_t)row * ROW_VEC4;
        float s = 0.f;
#pragma unroll
        for (int i = 0; i < ROW_VEC4 / 256; i++) {
            float4 v = xr[tid + i * 256];   // normal cached load: warms L2 with x
            s += (v.x + v.y) + (v.z + v.w);
        }
#pragma unroll
        for (int off = 16; off > 0; off >>= 1)
            s += __shfl_xor_sync(0xFFFFFFFF, s, off);
        if ((tid & 31) == 0) warp_sums[tid >> 5] = s;
        __syncthreads();
        if (tid == 0) {
            float tot = 0.f;
#pragma unroll
            for (int w = 0; w < 8; w++) tot += warp_sums[w];
            g_y[row] = tot * (1.0f / ROW_ELEMS);
        }
        __syncthreads();
    }

    // ---------------- Grid sync: elect last CTA ----------------
    if (tid == 0) {
        __threadfence();   // publish g_y
        unsigned int prev = atomicAdd(&g_cnt1, 1u);
        is_last = (prev == GRID - 1);
    }
    __syncthreads();

    // ---------------- Phase 2 (last CTA only): FC stack ----------------
    if (is_last) {
#pragma unroll
        for (int i = 0; i < NROWS / 256; i++)
            sh_y[tid + i * 256] = g_y[tid + i * 256];  // this CTA wrote/fenced; L2-coherent
        __syncthreads();

        if (tid < B * CS) {   // squeeze GEMV + LeakyReLU (128 dots)
            const int b = tid / CS;
            const int ss = tid % CS;
            const float* wrow = w1 + ss * C;
            const float* yrow = sh_y + b * C;
            float acc = 0.f;
#pragma unroll 8
            for (int c = 0; c < C; c++) acc += wrow[c] * yrow[c];
            acc += b1[ss];
            sh_y1[tid] = (acc >= 0.f) ? acc : NEG_SLOPE * acc;
        }
        __syncthreads();

#pragma unroll
        for (int i = 0; i < NROWS / 256; i++) {   // excite GEMV + sigmoid
            const int idx = tid + i * 256;        // idx = b*C + c
            const int b = idx / C;
            const int c = idx % C;
            const float* wrow = w2 + c * CS;
            const float* y1row = sh_y1 + b * CS;
            float acc = b2[c];
#pragma unroll
            for (int ss = 0; ss < CS; ss++) acc += wrow[ss] * y1row[ss];
            g_gate[idx] = 1.0f / (1.0f + __expf(-acc));
        }
        __syncthreads();
        if (tid == 0) {
            __threadfence();                 // publish g_gate
            atomicExch(&g_flag, 1u);         // release
        }
    }

    // ---------------- Wait for gates ----------------
    if (tid == 0) {
        while (atomicAdd(&g_flag, 0u) == 0u) __nanosleep(64);
    }
    __syncthreads();  // all threads see gates-ready; L1 untouched for g_gate this launch

    // ---------------- Phase 3: scale (x mostly L2-resident now) ----------------
#pragma unroll
    for (int r = 0; r < ROWS_PER_CTA; r++) {
        const int row = row0 + r;
        const float g = __ldcg(&g_gate[row]);   // L2 load, bypass L1
        const float4* __restrict__ xr =
            reinterpret_cast<const float4*>(x) + (size_t)row * ROW_VEC4;
        float4* __restrict__ orow =
            reinterpret_cast<float4*>(out) + (size_t)row * ROW_VEC4;
#pragma unroll
        for (int i = 0; i < ROW_VEC4 / 256; i++) {
            float4 v = __ldcs(&xr[tid + i * 256]);   // evict-first: last use of x
            v.x *= g; v.y *= g; v.z *= g; v.w *= g;
            __stcs(&orow[tid + i * 256], v);         // streaming store: don't evict x
        }
    }

    // ---------------- Self-reset for next graph replay ----------------
    if (tid == 0) {
        unsigned int prev = atomicAdd(&g_cnt2, 1u);
        if (prev == GRID - 1) {   // truly last: everyone already passed the flag wait
            g_cnt1 = 0u;
            g_cnt2 = 0u;
            g_flag = 0u;
            __threadfence();
        }
    }
}

extern "C" void kernel_launch(void* const* d_in, const int* in_sizes, int n_in,
                              void* d_out, int out_size) {
    const float* x  = (const float*)d_in[0];
    const float* w1 = (const float*)d_in[1];
    const float* b1 = (const float*)d_in[2];
    const float* w2 = (const float*)d_in[3];
    const float* b2 = (const float*)d_in[4];
    float* out = (float*)d_out;

    se_fused_kernel<<<GRID, 256>>>(x, w1, b1, w2, b2, out);
}

// round 4
// speedup vs baseline: 1.1496x; 1.1496x over previous
#include <cuda_runtime.h>

#define NEG_SLOPE 0.2f

// x: [B=8, C=256, H=128, W=128] f32
static constexpr int NROWS = 2048;      // B*C
static constexpr int ROW_ELEMS = 16384; // H*W
static constexpr int ROW_VEC4 = ROW_ELEMS / 4; // 4096
static constexpr int B = 8;
static constexpr int C = 256;
static constexpr int CS = 16;

__device__ float g_y[NROWS];     // pooled means
__device__ float g_gate[NROWS];  // sigmoid gates

// ---------------------------------------------------------------------------
// Kernel 1: global average pool. One CTA per row. Default cache policy so x
// lands in L2 (the tail of it will still be resident when scale starts).
// ---------------------------------------------------------------------------
__global__ __launch_bounds__(256) void gap_kernel(const float* __restrict__ x) {
    const int row = blockIdx.x;
    const float4* __restrict__ xr = reinterpret_cast<const float4*>(x) + (size_t)row * ROW_VEC4;
    const int tid = threadIdx.x;

    float s = 0.f;
#pragma unroll
    for (int i = 0; i < ROW_VEC4 / 256; i++) {
        float4 v = xr[tid + i * 256];
        s += (v.x + v.y) + (v.z + v.w);
    }

#pragma unroll
    for (int off = 16; off > 0; off >>= 1)
        s += __shfl_xor_sync(0xFFFFFFFF, s, off);

    __shared__ float warp_sums[8];
    if ((tid & 31) == 0) warp_sums[tid >> 5] = s;
    __syncthreads();
    if (tid == 0) {
        float tot = 0.f;
#pragma unroll
        for (int w = 0; w < 8; w++) tot += warp_sums[w];
        g_y[row] = tot * (1.0f / ROW_ELEMS);
    }
}

// ---------------------------------------------------------------------------
// Kernel 2: tiny FC stack (squeeze -> LeakyReLU -> excite -> sigmoid).
// Single CTA; ~2us. Kept separate: fusing it into gap's last CTA cost ~15us
// in round 2 (per-CTA fence/atomic tail), and full persistence cost more.
// ---------------------------------------------------------------------------
__global__ __launch_bounds__(256) void fc_kernel(const float* __restrict__ w1,
                                                 const float* __restrict__ b1,
                                                 const float* __restrict__ w2,
                                                 const float* __restrict__ b2) {
    __shared__ float sh_y[NROWS];   // 8 KB pooled means
    __shared__ float sh_y1[B * CS];

    const int tid = threadIdx.x;

#pragma unroll
    for (int i = 0; i < NROWS / 256; i++)
        sh_y[tid + i * 256] = g_y[tid + i * 256];
    __syncthreads();

    if (tid < B * CS) {
        const int b = tid / CS;
        const int s = tid % CS;
        const float* wrow = w1 + s * C;
        const float* yrow = sh_y + b * C;
        float acc = 0.f;
#pragma unroll 8
        for (int c = 0; c < C; c++) acc += wrow[c] * yrow[c];
        acc += b1[s];
        sh_y1[tid] = (acc >= 0.f) ? acc : NEG_SLOPE * acc;
    }
    __syncthreads();

#pragma unroll
    for (int i = 0; i < NROWS / 256; i++) {
        const int idx = tid + i * 256;  // idx = b*C + c
        const int b = idx / C;
        const int c = idx % C;
        const float* wrow = w2 + c * CS;
        const float* y1row = sh_y1 + b * CS;
        float acc = b2[c];
#pragma unroll
        for (int s = 0; s < CS; s++) acc += wrow[s] * y1row[s];
        g_gate[idx] = 1.0f / (1.0f + __expf(-acc));
    }
}

// ---------------------------------------------------------------------------
// Kernel 3: channel-wise scale.
//  - REVERSE row order: first-scheduled CTAs re-read the tail of x that gap
//    left L2-resident (proved worth ~18us in round 2).
//  - __ldcs on x: evict-first, this is x's last use.
//  - __stcs on out: streaming store, minimize eviction of still-unread x.
// ---------------------------------------------------------------------------
__global__ __launch_bounds__(256) void scale_kernel(const float* __restrict__ x,
                                                    float* __restrict__ out) {
    const int row = (NROWS - 1) - blockIdx.x;
    const float g = g_gate[row];
    const float4* __restrict__ xr = reinterpret_cast<const float4*>(x) + (size_t)row * ROW_VEC4;
    float4* __restrict__ orow = reinterpret_cast<float4*>(out) + (size_t)row * ROW_VEC4;
    const int tid = threadIdx.x;

#pragma unroll
    for (int i = 0; i < ROW_VEC4 / 256; i++) {
        float4 v = __ldcs(&xr[tid + i * 256]);
        v.x *= g; v.y *= g; v.z *= g; v.w *= g;
        __stcs(&orow[tid + i * 256], v);
    }
}

extern "C" void kernel_launch(void* const* d_in, const int* in_sizes, int n_in,
                              void* d_out, int out_size) {
    const float* x  = (const float*)d_in[0];
    const float* w1 = (const float*)d_in[1];
    const float* b1 = (const float*)d_in[2];
    const float* w2 = (const float*)d_in[3];
    const float* b2 = (const float*)d_in[4];
    float* out = (float*)d_out;

    gap_kernel<<<NROWS, 256>>>(x);
    fc_kernel<<<1, 256>>>(w1, b1, w2, b2);
    scale_kernel<<<NROWS, 256>>>(x, out);
}

// round 6
// speedup vs baseline: 1.1824x; 1.0286x over previous
#include <cuda_runtime.h>

#define NEG_SLOPE 0.2f

// x: [B=8, C=256, H=128, W=128] f32
static constexpr int NROWS = 2048;      // B*C
static constexpr int ROW_ELEMS = 16384; // H*W
static constexpr int ROW_VEC4 = ROW_ELEMS / 4; // 4096 float4 per row
static constexpr int ROW_VEC8 = ROW_ELEMS / 8; // 2048 float8 per row
static constexpr int B = 8;
static constexpr int C = 256;
static constexpr int CS = 16;

__device__ float g_y[NROWS];     // pooled means
__device__ float g_gate[NROWS];  // sigmoid gates

struct f8 { float a0,a1,a2,a3,a4,a5,a6,a7; };

// 32-byte load with L2 evict_last priority (sm_103 requires v8.b32/v4.b64 for
// this modifier). Pins x into L2 across the two passes.
__device__ __forceinline__ f8 ldg_evict_last_32B(const void* p) {
    unsigned long long d0, d1, d2, d3;
    asm("ld.global.L2::evict_last.v4.b64 {%0,%1,%2,%3}, [%4];"
        : "=l"(d0), "=l"(d1), "=l"(d2), "=l"(d3)
        : "l"(p));
    f8 r;
    r.a0 = __uint_as_float((unsigned)(d0));
    r.a1 = __uint_as_float((unsigned)(d0 >> 32));
    r.a2 = __uint_as_float((unsigned)(d1));
    r.a3 = __uint_as_float((unsigned)(d1 >> 32));
    r.a4 = __uint_as_float((unsigned)(d2));
    r.a5 = __uint_as_float((unsigned)(d2 >> 32));
    r.a6 = __uint_as_float((unsigned)(d3));
    r.a7 = __uint_as_float((unsigned)(d3 >> 32));
    return r;
}

// ---------------------------------------------------------------------------
// Kernel 1: global average pool. One CTA per row; 32B loads install x into L2
// with evict_last priority so scale's re-read mostly hits L2 (x=134MB vs
// L2=126MB; scale's normal-priority traffic won't evict the pinned lines).
// ---------------------------------------------------------------------------
__global__ __launch_bounds__(256) void gap_kernel(const float* __restrict__ x) {
    const int row = blockIdx.x;
    const char* __restrict__ xr =
        reinterpret_cast<const char*>(x) + (size_t)row * ROW_ELEMS * 4;
    const int tid = threadIdx.x;

    float s = 0.f;
    // 2048 float8 / 256 threads = 8 iterations, each warp covers 1KB contiguous
#pragma unroll
    for (int i = 0; i < ROW_VEC8 / 256; i++) {
        f8 v = ldg_evict_last_32B(xr + (size_t)(tid + i * 256) * 32);
        s += ((v.a0 + v.a1) + (v.a2 + v.a3)) + ((v.a4 + v.a5) + (v.a6 + v.a7));
    }

#pragma unroll
    for (int off = 16; off > 0; off >>= 1)
        s += __shfl_xor_sync(0xFFFFFFFF, s, off);

    __shared__ float warp_sums[8];
    if ((tid & 31) == 0) warp_sums[tid >> 5] = s;
    __syncthreads();
    if (tid == 0) {
        float tot = 0.f;
#pragma unroll
        for (int w = 0; w < 8; w++) tot += warp_sums[w];
        g_y[row] = tot * (1.0f / ROW_ELEMS);
    }
}

// ---------------------------------------------------------------------------
// Kernel 2: tiny FC stack (squeeze -> LeakyReLU -> excite -> sigmoid). ~2us.
// ---------------------------------------------------------------------------
__global__ __launch_bounds__(256) void fc_kernel(const float* __restrict__ w1,
                                                 const float* __restrict__ b1,
                                                 const float* __restrict__ w2,
                                                 const float* __restrict__ b2) {
    __shared__ float sh_y[NROWS];   // 8 KB pooled means
    __shared__ float sh_y1[B * CS];

    const int tid = threadIdx.x;

#pragma unroll
    for (int i = 0; i < NROWS / 256; i++)
        sh_y[tid + i * 256] = g_y[tid + i * 256];
    __syncthreads();

    if (tid < B * CS) {
        const int b = tid / CS;
        const int s = tid % CS;
        const float* wrow = w1 + s * C;
        const float* yrow = sh_y + b * C;
        float acc = 0.f;
#pragma unroll 8
        for (int c = 0; c < C; c++) acc += wrow[c] * yrow[c];
        acc += b1[s];
        sh_y1[tid] = (acc >= 0.f) ? acc : NEG_SLOPE * acc;
    }
    __syncthreads();

#pragma unroll
    for (int i = 0; i < NROWS / 256; i++) {
        const int idx = tid + i * 256;  // idx = b*C + c
        const int b = idx / C;
        const int c = idx % C;
        const float* wrow = w2 + c * CS;
        const float* y1row = sh_y1 + b * CS;
        float acc = b2[c];
#pragma unroll
        for (int s = 0; s < CS; s++) acc += wrow[s] * y1row[s];
        g_gate[idx] = 1.0f / (1.0f + __expf(-acc));
    }
}

// ---------------------------------------------------------------------------
// Kernel 3: channel-wise scale. Reverse row order (worth ~18us, round 2),
// PLAIN load/store policy (the .cs hints in round 4 cost ~16us — reverted).
// ---------------------------------------------------------------------------
__global__ __launch_bounds__(256) void scale_kernel(const float* __restrict__ x,
                                                    float* __restrict__ out) {
    const int row = (NROWS - 1) - blockIdx.x;
    const float g = g_gate[row];
    const float4* __restrict__ xr = reinterpret_cast<const float4*>(x) + (size_t)row * ROW_VEC4;
    float4* __restrict__ orow = reinterpret_cast<float4*>(out) + (size_t)row * ROW_VEC4;
    const int tid = threadIdx.x;

#pragma unroll
    for (int i = 0; i < ROW_VEC4 / 256; i++) {
        float4 v = xr[tid + i * 256];
        v.x *= g; v.y *= g; v.z *= g; v.w *= g;
        orow[tid + i * 256] = v;
    }
}

extern "C" void kernel_launch(void* const* d_in, const int* in_sizes, int n_in,
                              void* d_out, int out_size) {
    const float* x  = (const float*)d_in[0];
    const float* w1 = (const float*)d_in[1];
    const float* b1 = (const float*)d_in[2];
    const float* w2 = (const float*)d_in[3];
    const float* b2 = (const float*)d_in[4];
    float* out = (float*)d_out;

    gap_kernel<<<NROWS, 256>>>(x);
    fc_kernel<<<1, 256>>>(w1, b1, w2, b2);
    scale_kernel<<<NROWS, 256>>>(x, out);
}

// round 7
// speedup vs baseline: 1.3014x; 1.1006x over previous
#include <cuda_runtime.h>

#define NEG_SLOPE 0.2f

// x: [B=8, C=256, H=128, W=128] f32. row = b*C+c.
static constexpr int NROWS = 2048;
static constexpr int ROW_ELEMS = 16384;          // H*W
static constexpr int ROW_VEC4 = ROW_ELEMS / 4;   // 4096
static constexpr int C = 256;
static constexpr int CS = 16;

static constexpr int GROUP_ROWS = 512;           // 2 batches = 33.5 MB
static constexpr int NGROUPS = NROWS / GROUP_ROWS; // 4

__device__ float g_y[NROWS];   // pooled means, produced by gap role

// ---------------------------------------------------------------------------
// Pipelined step kernel.
//   CTAs [0, 512):     scale group (step-1)  [active when step >= 1]
//                      (inline FC: recompute gate for own row; x of that group
//                       is L2-resident from the previous step's gap reads)
//   CTAs [512, 1024):  gap (pool) group step [active when step < NGROUPS]
// Kernel-boundary ordering makes g_y safe; no grid sync, no atomics.
// ---------------------------------------------------------------------------
__global__ __launch_bounds__(256) void pipe_kernel(const float* __restrict__ x,
                                                   const float* __restrict__ w1,
                                                   const float* __restrict__ b1,
                                                   const float* __restrict__ w2,
                                                   const float* __restrict__ b2,
                                                   float* __restrict__ out,
                                                   int step) {
    const int tid = threadIdx.x;
    const int bid = blockIdx.x;

    if (bid >= GROUP_ROWS) {
        // ---------------- GAP role: pool one row of group `step` ----------------
        if (step >= NGROUPS) return;
        const int row = step * GROUP_ROWS + (bid - GROUP_ROWS);
        const float4* __restrict__ xr =
            reinterpret_cast<const float4*>(x) + (size_t)row * ROW_VEC4;

        float s = 0.f;
#pragma unroll
        for (int i = 0; i < ROW_VEC4 / 256; i++) {
            float4 v = xr[tid + i * 256];
            s += (v.x + v.y) + (v.z + v.w);
        }
#pragma unroll
        for (int off = 16; off > 0; off >>= 1)
            s += __shfl_xor_sync(0xFFFFFFFF, s, off);

        __shared__ float warp_sums[8];
        if ((tid & 31) == 0) warp_sums[tid >> 5] = s;
        __syncthreads();
        if (tid == 0) {
            float tot = 0.f;
#pragma unroll
            for (int w = 0; w < 8; w++) tot += warp_sums[w];
            g_y[row] = tot * (1.0f / ROW_ELEMS);
        }
        return;
    }

    // ---------------- SCALE role: gate + scale one row of group `step-1` ----------------
    if (step < 1) return;
    const int row = (step - 1) * GROUP_ROWS + bid;
    const int b = row / C;
    const int c = row % C;

    // Inline FC: y1[s] = leaky(w1[s,:]·y[b,:] + b1[s]), s=0..15, cooperatively.
    // thread t: s = t>>4 handles lane group, cc = t&15 strides over c.
    __shared__ float sh_y1[CS];
    __shared__ float sh_gate;
    {
        const int s_idx = tid >> 4;   // 0..15
        const int cc = tid & 15;      // 0..15
        const float* __restrict__ yb = g_y + b * C;
        const float* __restrict__ wrow = w1 + s_idx * C;
        float part = 0.f;
#pragma unroll
        for (int k = 0; k < C / 16; k++) {
            const int cidx = cc + k * 16;
            part += wrow[cidx] * yb[cidx];
        }
        // reduce within 16-lane segments
#pragma unroll
        for (int off = 8; off > 0; off >>= 1)
            part += __shfl_down_sync(0xFFFFFFFF, part, off, 16);
        if (cc == 0) {
            part += b1[s_idx];
            sh_y1[s_idx] = (part >= 0.f) ? part : NEG_SLOPE * part;
        }
    }
    __syncthreads();
    if (tid == 0) {
        const float* __restrict__ w2row = w2 + c * CS;
        float acc = b2[c];
#pragma unroll
        for (int s = 0; s < CS; s++) acc += w2row[s] * sh_y1[s];
        sh_gate = 1.0f / (1.0f + __expf(-acc));
    }
    __syncthreads();
    const float g = sh_gate;

    const float4* __restrict__ xr =
        reinterpret_cast<const float4*>(x) + (size_t)row * ROW_VEC4;
    float4* __restrict__ orow =
        reinterpret_cast<float4*>(out) + (size_t)row * ROW_VEC4;
#pragma unroll
    for (int i = 0; i < ROW_VEC4 / 256; i++) {
        float4 v = xr[tid + i * 256];   // mostly L2 hits: read by previous step's gap
        v.x *= g; v.y *= g; v.z *= g; v.w *= g;
        orow[tid + i * 256] = v;
    }
}

extern "C" void kernel_launch(void* const* d_in, const int* in_sizes, int n_in,
                              void* d_out, int out_size) {
    const float* x  = (const float*)d_in[0];
    const float* w1 = (const float*)d_in[1];
    const float* b1 = (const float*)d_in[2];
    const float* w2 = (const float*)d_in[3];
    const float* b2 = (const float*)d_in[4];
    float* out = (float*)d_out;

    // steps: 0 = gap(g0); 1..3 = scale(g-1)+gap(g); 4 = scale(g3)
    for (int step = 0; step <= NGROUPS; step++) {
        pipe_kernel<<<2 * GROUP_ROWS, 256>>>(x, w1, b1, w2, b2, out, step);
    }
}

// round 8
// speedup vs baseline: 1.3400x; 1.0297x over previous
#include <cuda_runtime.h>

#define NEG_SLOPE 0.2f

// x: [B=8, C=256, H=128, W=128] f32. row = b*C+c.
static constexpr int NROWS = 2048;
static constexpr int ROW_ELEMS = 16384;          // H*W
static constexpr int ROW_VEC4 = ROW_ELEMS / 4;   // 4096
static constexpr int HALF_VEC4 = ROW_VEC4 / 2;   // 2048
static constexpr int C = 256;
static constexpr int CS = 16;

static constexpr int GROUP_ROWS = 512;           // 2 batches = 33.5 MB
static constexpr int NGROUPS = NROWS / GROUP_ROWS; // 4

static constexpr int SCALE_CTAS = 2 * GROUP_ROWS; // 1024: two CTAs per scale row
static constexpr int GAP_CTAS = GROUP_ROWS;       // 512: one CTA per gap row
static constexpr int GRID = SCALE_CTAS + GAP_CTAS; // 1536

__device__ float g_y[NROWS];   // pooled means

// ---------------------------------------------------------------------------
// Pipelined step kernel, byte-balanced roles (~64KB moved per CTA):
//   bid in [0, 1024):    scale HALF-row of group (step-1): 32KB rd + 32KB wr
//   bid in [1024, 1536): gap (pool) one row of group step: 64KB rd
// Kernel-boundary ordering makes g_y safe; no grid sync, no atomics.
// ---------------------------------------------------------------------------
__global__ __launch_bounds__(256) void pipe_kernel(const float* __restrict__ x,
                                                   const float* __restrict__ w1,
                                                   const float* __restrict__ b1,
                                                   const float* __restrict__ w2,
                                                   const float* __restrict__ b2,
                                                   float* __restrict__ out,
                                                   int step) {
    const int tid = threadIdx.x;
    const int bid = blockIdx.x;

    if (bid >= SCALE_CTAS) {
        // ---------------- GAP role: pool one row of group `step` ----------------
        if (step >= NGROUPS) return;
        const int row = step * GROUP_ROWS + (bid - SCALE_CTAS);
        const float4* __restrict__ xr =
            reinterpret_cast<const float4*>(x) + (size_t)row * ROW_VEC4;

        float s = 0.f;
#pragma unroll
        for (int i = 0; i < ROW_VEC4 / 256; i++) {
            float4 v = xr[tid + i * 256];
            s += (v.x + v.y) + (v.z + v.w);
        }
#pragma unroll
        for (int off = 16; off > 0; off >>= 1)
            s += __shfl_xor_sync(0xFFFFFFFF, s, off);

        __shared__ float warp_sums[8];
        if ((tid & 31) == 0) warp_sums[tid >> 5] = s;
        __syncthreads();
        if (tid == 0) {
            float tot = 0.f;
#pragma unroll
            for (int w = 0; w < 8; w++) tot += warp_sums[w];
            g_y[row] = tot * (1.0f / ROW_ELEMS);
        }
        return;
    }

    // ------------- SCALE role: gate + scale half a row of group `step-1` -------------
    if (step < 1) return;
    const int row = (step - 1) * GROUP_ROWS + (bid >> 1);
    const int half = bid & 1;
    const int b = row / C;
    const int c = row % C;

    // Inline FC (redundant per CTA; FMA pipe is idle anyway):
    // y1[s] = leaky(w1[s,:]·y[b,:] + b1[s]); gate = sigmoid(w2[c,:]·y1 + b2[c])
    __shared__ float sh_y1[CS];
    __shared__ float sh_gate;
    {
        const int s_idx = tid >> 4;   // 0..15
        const int cc = tid & 15;      // 0..15
        const float* __restrict__ yb = g_y + b * C;
        const float* __restrict__ wrow = w1 + s_idx * C;
        float part = 0.f;
#pragma unroll
        for (int k = 0; k < C / 16; k++) {
            const int cidx = cc + k * 16;
            part += wrow[cidx] * yb[cidx];
        }
#pragma unroll
        for (int off = 8; off > 0; off >>= 1)
            part += __shfl_down_sync(0xFFFFFFFF, part, off, 16);
        if (cc == 0) {
            part += b1[s_idx];
            sh_y1[s_idx] = (part >= 0.f) ? part : NEG_SLOPE * part;
        }
    }
    __syncthreads();
    if (tid == 0) {
        const float* __restrict__ w2row = w2 + c * CS;
        float acc = b2[c];
#pragma unroll
        for (int s = 0; s < CS; s++) acc += w2row[s] * sh_y1[s];
        sh_gate = 1.0f / (1.0f + __expf(-acc));
    }
    __syncthreads();
    const float g = sh_gate;

    const size_t base = (size_t)row * ROW_VEC4 + (size_t)half * HALF_VEC4;
    const float4* __restrict__ xr = reinterpret_cast<const float4*>(x) + base;
    float4* __restrict__ orow = reinterpret_cast<float4*>(out) + base;
#pragma unroll
    for (int i = 0; i < HALF_VEC4 / 256; i++) {   // 8 iterations
        float4 v = xr[tid + i * 256];   // mostly L2 hits (read by previous step's gap)
        v.x *= g; v.y *= g; v.z *= g; v.w *= g;
        orow[tid + i * 256] = v;
    }
}

extern "C" void kernel_launch(void* const* d_in, const int* in_sizes, int n_in,
                              void* d_out, int out_size) {
    const float* x  = (const float*)d_in[0];
    const float* w1 = (const float*)d_in[1];
    const float* b1 = (const float*)d_in[2];
    const float* w2 = (const float*)d_in[3];
    const float* b2 = (const float*)d_in[4];
    float* out = (float*)d_out;

    // steps: 0 = gap(g0); 1..3 = scale(g-1)+gap(g); 4 = scale(g3)
    for (int step = 0; step <= NGROUPS; step++) {
        pipe_kernel<<<GRID, 256>>>(x, w1, b1, w2, b2, out, step);
    }
}